// round 15
// baseline (speedup 1.0000x reference)
#include <cuda_runtime.h>
#include <cuda_fp16.h>
#include <cstdint>

#define NN 100000
#define NE 1000000
#define D  128

// ---------------- scratch (device globals; no allocations allowed) ----------
__device__ int    g_cnt[NN + 1];
__device__ int    g_off[NN + 2];
__device__ int    g_rank[NE];                // edge's rank within its dst bucket
__device__ int    g_srcs[NE];
__device__ int    g_part[128];
__device__ __half g_xh   [(size_t)NN * D];   // fp16 copy of input x
__device__ __half g_meanh[(size_t)NN * D];
__device__ __half g_x1h  [(size_t)NN * D];
__device__ __half g_P    [(size_t)NN * 16];  // fp16, P + b_o folded
__device__ __half g_Q    [(size_t)NN * 16];  // fp16
// fp16 weights (pre-converted once per call)
__device__ __half g_wl0h[128 * 128];
__device__ __half g_wr0h[128 * 128];
__device__ __half g_wl1h[128 * 128];
__device__ __half g_wr1h[128 * 128];
__device__ __half g_wch [128 * 256];
__device__ __half g_woh [32 * 128];          // r<16 = Wo[r][0:128], r>=16 = Wo[r-16][128:256]

// ---------------- helpers ----------------------------------------------------
__device__ __forceinline__ uint32_t smem_u32(const void* p) {
    uint32_t a;
    asm("{ .reg .u64 t; cvta.to.shared.u64 t, %1; cvt.u32.u64 %0, t; }"
        : "=r"(a) : "l"(p));
    return a;
}
__device__ __forceinline__ uint32_t pkh(float lo, float hi) {
    uint32_t d;  // bits[15:0]=f16(lo), bits[31:16]=f16(hi)
    asm("cvt.rn.f16x2.f32 %0, %1, %2;" : "=r"(d) : "f"(hi), "f"(lo));
    return d;
}
__device__ __forceinline__ void ldsm4(uint32_t* r, uint32_t addr) {
    asm volatile("ldmatrix.sync.aligned.m8n8.x4.shared.b16 {%0,%1,%2,%3}, [%4];"
                 : "=r"(r[0]), "=r"(r[1]), "=r"(r[2]), "=r"(r[3]) : "r"(addr));
}
__device__ __forceinline__ void mma_f16(float* d, const uint32_t* a,
                                        const uint32_t* b) {
    asm volatile(
        "mma.sync.aligned.m16n8k16.row.col.f32.f16.f16.f32 "
        "{%0,%1,%2,%3}, {%4,%5,%6,%7}, {%8,%9}, {%0,%1,%2,%3};"
        : "+f"(d[0]), "+f"(d[1]), "+f"(d[2]), "+f"(d[3])
        : "r"(a[0]), "r"(a[1]), "r"(a[2]), "r"(a[3]), "r"(b[0]), "r"(b[1]));
}

// ---------------- prep: x->fp16, weights->fp16, degree count + rank ---------
// g_cnt is zeroed by cudaMemsetAsync BEFORE this kernel.
__global__ void k_prep(const float* __restrict__ x, const int* __restrict__ ei,
                       const float* __restrict__ wl0, const float* __restrict__ wr0,
                       const float* __restrict__ wl1, const float* __restrict__ wr1,
                       const float* __restrict__ wc,  const float* __restrict__ wo) {
    int i = blockIdx.x * blockDim.x + threadIdx.x;
    if (i < NN * 32) {           // x: one float4 -> 4 halves
        float4 v = reinterpret_cast<const float4*>(x)[i];
        uint2 h;
        h.x = pkh(v.x, v.y);
        h.y = pkh(v.z, v.w);
        reinterpret_cast<uint2*>(g_xh)[i] = h;
    }
    if (i < NE) {                // count in-degree; atomic returns bucket rank
        unsigned d = (unsigned)ei[NE + i];
        if (d < NN) g_rank[i] = atomicAdd(&g_cnt[d], 1);
    }
    if (i < 16384)       g_wl0h[i]         = __float2half(wl0[i]);
    else if (i < 32768)  g_wr0h[i - 16384] = __float2half(wr0[i - 16384]);
    else if (i < 49152)  g_wl1h[i - 32768] = __float2half(wl1[i - 32768]);
    else if (i < 65536)  g_wr1h[i - 49152] = __float2half(wr1[i - 49152]);
    else if (i < 98304)  g_wch[i - 65536]  = __float2half(wc[i - 65536]);
    else if (i < 102400) {       // Wo rearranged to [32,128]
        int j = i - 98304;
        int r = j >> 7, c = j & 127;
        float v = (r < 16) ? wo[(size_t)r * 256 + c]
                           : wo[(size_t)(r - 16) * 256 + 128 + c];
        g_woh[j] = __float2half(v);
    }
}

// ---------------- CSR scans + atomic-free fill -------------------------------
__global__ void k_scan_block() {   // per-block exclusive scan of g_cnt -> g_off
    __shared__ int sh[1024];
    int i = blockIdx.x * 1024 + threadIdx.x;
    int v = (i < NN) ? g_cnt[i] : 0;
    sh[threadIdx.x] = v;
    __syncthreads();
    for (int off = 1; off < 1024; off <<= 1) {
        int t = (threadIdx.x >= off) ? sh[threadIdx.x - off] : 0;
        __syncthreads();
        sh[threadIdx.x] += t;
        __syncthreads();
    }
    if (i < NN) g_off[i] = sh[threadIdx.x] - v;   // exclusive
    if (threadIdx.x == 1023) g_part[blockIdx.x] = sh[1023];
}

__global__ void k_scan_add() {   // parallel scan over block partials
    __shared__ int sp[128];
    int b = blockIdx.x;
    int nb = gridDim.x;
    if (threadIdx.x < 128)
        sp[threadIdx.x] = (threadIdx.x < nb) ? g_part[threadIdx.x] : 0;
    __syncthreads();
    for (int off = 1; off < 128; off <<= 1) {
        int t = 0;
        if (threadIdx.x < 128 && threadIdx.x >= off) t = sp[threadIdx.x - off];
        __syncthreads();
        if (threadIdx.x < 128) sp[threadIdx.x] += t;
        __syncthreads();
    }
    int s_base = (b == 0) ? 0 : sp[b - 1];
    int i = b * 1024 + threadIdx.x;
    if (i < NN) g_off[i] += s_base;
    if (i == 0) g_off[NN] = NE;
}

__global__ void k_fill(const int* __restrict__ ei) {   // no atomics
    int e = blockIdx.x * blockDim.x + threadIdx.x;
    if (e < NE) {
        unsigned d = (unsigned)ei[NE + e];
        if (d < NN) {
            int p = g_off[d] + g_rank[e];
            if (p >= 0 && p < NE) g_srcs[p] = ei[e];
        }
    }
}

// ---------------- mean aggregation (fp16 rows): one warp per node ------------
__global__ void k_aggregate(const __half* __restrict__ xin,
                            __half* __restrict__ mout) {
    int n = blockIdx.x * (blockDim.x >> 5) + (threadIdx.x >> 5);
    if (n >= NN) return;
    int lane = threadIdx.x & 31;
    int beg = g_off[n], end = g_off[n + 1];
    float ax = 0.f, ay = 0.f, az = 0.f, aw = 0.f;
    #pragma unroll 4
    for (int t = beg; t < end; t++) {
        unsigned s = (unsigned)g_srcs[t];
        if (s >= NN) continue;
        uint2 v = *reinterpret_cast<const uint2*>(xin + (size_t)s * D + lane * 4);
        __half2 h0 = *reinterpret_cast<__half2*>(&v.x);
        __half2 h1 = *reinterpret_cast<__half2*>(&v.y);
        float2 f0 = __half22float2(h0), f1 = __half22float2(h1);
        ax += f0.x; ay += f0.y; az += f1.x; aw += f1.y;
    }
    int c = end - beg;
    float inv = 1.0f / (float)(c > 0 ? c : 1);
    uint2 o;
    o.x = pkh(ax * inv, ay * inv);
    o.y = pkh(az * inv, aw * inv);
    *reinterpret_cast<uint2*>(mout + (size_t)n * D + lane * 4) = o;
}

// ---------------- fused SAGE layer (+ optional fused P/Q head) ---------------
// h = relu([mean|x]W^T + bl) (SMEM only); x' = relu([x|h]Wc^T + bc).
// do_pq=0: write x' to OUT. do_pq=1: x' -> SMEM, then P/Q = x' x Wo^T (+b_o).
#define SROW   272
#define SX_OFF 0
#define SMH_OFF 34816
#define SB_OFF 69632
#define SM_TOT 104448

struct MmaCtx {
    uint32_t smb, aoff, boff;
    int m0, n0;
};

__device__ __forceinline__ void mma_tiles(const MmaCtx& c, uint32_t a_off_base,
                                          float acc[2][8][4]) {
    #pragma unroll
    for (int ks = 0; ks < 8; ks++) {
        uint32_t a0[4], a1[4], bf[4][4];
        ldsm4(a0, c.smb + a_off_base + (uint32_t)(c.m0 * SROW) + ks * 32 + c.aoff);
        ldsm4(a1, c.smb + a_off_base + (uint32_t)((c.m0 + 16) * SROW) + ks * 32 + c.aoff);
        #pragma unroll
        for (int nb = 0; nb < 4; nb++)
            ldsm4(bf[nb], c.smb + SB_OFF + (uint32_t)((c.n0 + nb * 16) * SROW)
                          + ks * 32 + c.boff);
        #pragma unroll
        for (int nb = 0; nb < 4; nb++) {
            mma_f16(acc[0][nb * 2 + 0], a0, &bf[nb][0]);
            mma_f16(acc[0][nb * 2 + 1], a0, &bf[nb][2]);
            mma_f16(acc[1][nb * 2 + 0], a1, &bf[nb][0]);
            mma_f16(acc[1][nb * 2 + 1], a1, &bf[nb][2]);
        }
    }
}

__device__ __forceinline__ void load_b(char* sm, const __half* __restrict__ w,
                                       int stride, int tid) {
    #pragma unroll
    for (int i = 0; i < 8; i++) {
        int idx = tid + i * 256;          // 0..2047
        int r = idx >> 4, cc = idx & 15;
        uint4 v = *reinterpret_cast<const uint4*>(w + (size_t)r * stride + cc * 8);
        *reinterpret_cast<uint4*>(sm + SB_OFF + r * SROW + cc * 16) = v;
    }
}

__global__ void __launch_bounds__(256, 2) k_layer(
    const __half* __restrict__ X, const __half* __restrict__ MEAN,
    const __half* __restrict__ Wl, const __half* __restrict__ Wr,
    const __half* __restrict__ Wc, const __half* __restrict__ Wo,
    const float* __restrict__ bl, const float* __restrict__ bc,
    const float* __restrict__ bo,
    __half* __restrict__ OUT, int nrows, int do_pq)
{
    extern __shared__ __align__(16) char sm[];
    uint32_t smb = smem_u32(sm);
    int tid = threadIdx.x, lane = tid & 31, wid = tid >> 5;
    int row0 = blockIdx.x * 128;

    MmaCtx c;
    c.smb = smb;
    c.m0 = (wid >> 1) * 32;
    c.n0 = (wid & 1) * 64;
    {
        int t = lane >> 3, rr = lane & 7;
        c.aoff = (uint32_t)((lane & 15) * SROW + (lane >> 4) * 16);
        c.boff = (uint32_t)((((t >> 1) * 8 + rr) * SROW) + (t & 1) * 16);
    }

    // load x and mean tiles (fp16 straight copies)
    #pragma unroll
    for (int i = 0; i < 8; i++) {
        int idx = tid + i * 256;
        int r = idx >> 4, cc = idx & 15;
        int gr = row0 + r;
        uint4 vx = make_uint4(0u, 0u, 0u, 0u), vm = vx;
        if (gr < nrows) {
            vx = *reinterpret_cast<const uint4*>(X + (size_t)gr * D + cc * 8);
            vm = *reinterpret_cast<const uint4*>(MEAN + (size_t)gr * D + cc * 8);
        }
        *reinterpret_cast<uint4*>(sm + SX_OFF + r * SROW + cc * 16) = vx;
        *reinterpret_cast<uint4*>(sm + SMH_OFF + r * SROW + cc * 16) = vm;
    }
    load_b(sm, Wl, 128, tid);
    __syncthreads();

    float acc[2][8][4];
    #pragma unroll
    for (int i = 0; i < 2; i++)
        #pragma unroll
        for (int j = 0; j < 8; j++)
            #pragma unroll
            for (int q = 0; q < 4; q++) acc[i][j][q] = 0.f;

    // GEMM1 phase a: mean x Wl
    mma_tiles(c, SMH_OFF, acc);
    __syncthreads();
    load_b(sm, Wr, 128, tid);
    __syncthreads();
    // GEMM1 phase b: x x Wr
    mma_tiles(c, SX_OFF, acc);

    // epilogue 1: h = relu(acc + bl) -> SMEM (overwrites mean tile)
    #pragma unroll
    for (int mi = 0; mi < 2; mi++) {
        int r0 = c.m0 + mi * 16 + (lane >> 2);
        #pragma unroll
        for (int f = 0; f < 8; f++) {
            int col = c.n0 + f * 8 + (lane & 3) * 2;
            float2 bv = *reinterpret_cast<const float2*>(bl + col);
            uint32_t h0 = pkh(fmaxf(acc[mi][f][0] + bv.x, 0.f),
                              fmaxf(acc[mi][f][1] + bv.y, 0.f));
            uint32_t h1 = pkh(fmaxf(acc[mi][f][2] + bv.x, 0.f),
                              fmaxf(acc[mi][f][3] + bv.y, 0.f));
            *reinterpret_cast<uint32_t*>(sm + SMH_OFF + r0 * SROW + col * 2) = h0;
            *reinterpret_cast<uint32_t*>(sm + SMH_OFF + (r0 + 8) * SROW + col * 2) = h1;
        }
    }
    __syncthreads();
    load_b(sm, Wc, 256, tid);          // Wc k-cols [0,128) -> multiplies x
    __syncthreads();

    #pragma unroll
    for (int i = 0; i < 2; i++)
        #pragma unroll
        for (int j = 0; j < 8; j++)
            #pragma unroll
            for (int q = 0; q < 4; q++) acc[i][j][q] = 0.f;

    // GEMM2 phase a: x x Wc1
    mma_tiles(c, SX_OFF, acc);
    __syncthreads();
    load_b(sm, Wc + 128, 256, tid);    // Wc k-cols [128,256) -> multiplies h
    __syncthreads();
    // GEMM2 phase b: h x Wc2
    mma_tiles(c, SMH_OFF, acc);

    if (!do_pq) {
        // epilogue 2: x' = relu(acc + bc) -> global fp16
        #pragma unroll
        for (int mi = 0; mi < 2; mi++) {
            int gr0 = row0 + c.m0 + mi * 16 + (lane >> 2);
            #pragma unroll
            for (int f = 0; f < 8; f++) {
                int col = c.n0 + f * 8 + (lane & 3) * 2;
                float2 bv = *reinterpret_cast<const float2*>(bc + col);
                if (gr0 < nrows) {
                    uint32_t h = pkh(fmaxf(acc[mi][f][0] + bv.x, 0.f),
                                     fmaxf(acc[mi][f][1] + bv.y, 0.f));
                    *reinterpret_cast<uint32_t*>(OUT + (size_t)gr0 * D + col) = h;
                }
                if (gr0 + 8 < nrows) {
                    uint32_t h = pkh(fmaxf(acc[mi][f][2] + bv.x, 0.f),
                                     fmaxf(acc[mi][f][3] + bv.y, 0.f));
                    *reinterpret_cast<uint32_t*>(OUT + (size_t)(gr0 + 8) * D + col) = h;
                }
            }
        }
        return;
    }

    // ---- fused P/Q head: x' -> SMEM (SX region), then [128x128] x Wo^T -----
    __syncthreads();
    #pragma unroll
    for (int mi = 0; mi < 2; mi++) {
        int r0 = c.m0 + mi * 16 + (lane >> 2);
        #pragma unroll
        for (int f = 0; f < 8; f++) {
            int col = c.n0 + f * 8 + (lane & 3) * 2;
            float2 bv = *reinterpret_cast<const float2*>(bc + col);
            uint32_t h0 = pkh(fmaxf(acc[mi][f][0] + bv.x, 0.f),
                              fmaxf(acc[mi][f][1] + bv.y, 0.f));
            uint32_t h1 = pkh(fmaxf(acc[mi][f][2] + bv.x, 0.f),
                              fmaxf(acc[mi][f][3] + bv.y, 0.f));
            *reinterpret_cast<uint32_t*>(sm + SX_OFF + r0 * SROW + col * 2) = h0;
            *reinterpret_cast<uint32_t*>(sm + SX_OFF + (r0 + 8) * SROW + col * 2) = h1;
        }
    }
    // Wo tile: 32 rows x 128 halves
    #pragma unroll
    for (int i = 0; i < 2; i++) {
        int idx = tid + i * 256;          // 0..511
        int r = idx >> 4, cc = idx & 15;
        uint4 v = *reinterpret_cast<const uint4*>(Wo + (size_t)r * 128 + cc * 8);
        *reinterpret_cast<uint4*>(sm + SB_OFF + r * SROW + cc * 16) = v;
    }
    __syncthreads();

    int m0 = wid * 16;
    float pq[4][4];
    #pragma unroll
    for (int j = 0; j < 4; j++)
        #pragma unroll
        for (int q = 0; q < 4; q++) pq[j][q] = 0.f;

    #pragma unroll
    for (int ks = 0; ks < 8; ks++) {
        uint32_t a0[4], bf[2][4];
        ldsm4(a0, smb + SX_OFF + (uint32_t)(m0 * SROW) + ks * 32 + c.aoff);
        ldsm4(bf[0], smb + SB_OFF + ks * 32 + c.boff);
        ldsm4(bf[1], smb + SB_OFF + (uint32_t)(16 * SROW) + ks * 32 + c.boff);
        mma_f16(pq[0], a0, &bf[0][0]);
        mma_f16(pq[1], a0, &bf[0][2]);
        mma_f16(pq[2], a0, &bf[1][0]);
        mma_f16(pq[3], a0, &bf[1][2]);
    }

    // epilogue: cols 0..15 -> P (+= b_o, fp16), cols 16..31 -> Q (fp16)
    int gr0 = row0 + m0 + (lane >> 2);
    #pragma unroll
    for (int f = 0; f < 4; f++) {
        int col = f * 8 + (lane & 3) * 2;   // 0..30
        #pragma unroll
        for (int half = 0; half < 2; half++) {
            int gr = gr0 + half * 8;
            if (gr >= nrows) continue;
            float vx = pq[f][half * 2 + 0];
            float vy = pq[f][half * 2 + 1];
            if (col < 16) {
                float2 bv = *reinterpret_cast<const float2*>(bo + col);
                uint32_t h = pkh(vx + bv.x, vy + bv.y);
                *reinterpret_cast<uint32_t*>(g_P + (size_t)gr * 16 + col) = h;
            } else {
                uint32_t h = pkh(vx, vy);
                *reinterpret_cast<uint32_t*>(g_Q + (size_t)gr * 16 + (col - 16)) = h;
            }
        }
    }
}

// ---------------- edge head: out[e] = P'[src] + Q[dst] (fp16 rows) -----------
__global__ void k_edge(const int* __restrict__ ei, float* __restrict__ out) {
    int t = blockIdx.x * blockDim.x + threadIdx.x;
    if (t >= NE * 2) return;
    int e = t >> 1, q = t & 1;           // q: which 8-class half
    unsigned s = (unsigned)ei[e];
    unsigned d = (unsigned)ei[NE + e];
    uint4 ph = make_uint4(0u, 0u, 0u, 0u), qh = ph;
    if (s < NN) ph = *reinterpret_cast<const uint4*>(g_P + (size_t)s * 16 + q * 8);
    if (d < NN) qh = *reinterpret_cast<const uint4*>(g_Q + (size_t)d * 16 + q * 8);
    float4 o0, o1;
    {
        float2 p0 = __half22float2(*reinterpret_cast<__half2*>(&ph.x));
        float2 p1 = __half22float2(*reinterpret_cast<__half2*>(&ph.y));
        float2 p2 = __half22float2(*reinterpret_cast<__half2*>(&ph.z));
        float2 p3 = __half22float2(*reinterpret_cast<__half2*>(&ph.w));
        float2 q0 = __half22float2(*reinterpret_cast<__half2*>(&qh.x));
        float2 q1 = __half22float2(*reinterpret_cast<__half2*>(&qh.y));
        float2 q2 = __half22float2(*reinterpret_cast<__half2*>(&qh.z));
        float2 q3 = __half22float2(*reinterpret_cast<__half2*>(&qh.w));
        o0.x = p0.x + q0.x; o0.y = p0.y + q0.y;
        o0.z = p1.x + q1.x; o0.w = p1.y + q1.y;
        o1.x = p2.x + q2.x; o1.y = p2.y + q2.y;
        o1.z = p3.x + q3.x; o1.w = p3.y + q3.y;
    }
    float4* dst = reinterpret_cast<float4*>(out) + (size_t)e * 4 + q * 2;
    __stcs(dst, o0);
    __stcs(dst + 1, o1);
}

// ---------------- launch -----------------------------------------------------
extern "C" void kernel_launch(void* const* d_in, const int* in_sizes, int n_in,
                              void* d_out, int out_size) {
    const float* x    = (const float*)d_in[0];
    const int*   ei   = (const int*)d_in[1];     // int32: JAX x64 is disabled
    const float* W_l0 = (const float*)d_in[2];
    const float* b_l0 = (const float*)d_in[3];
    const float* W_r0 = (const float*)d_in[4];
    const float* W_l1 = (const float*)d_in[5];
    const float* b_l1 = (const float*)d_in[6];
    const float* W_r1 = (const float*)d_in[7];
    const float* W_c  = (const float*)d_in[8];
    const float* b_c  = (const float*)d_in[9];
    const float* W_o  = (const float*)d_in[10];
    const float* b_o  = (const float*)d_in[11];
    float*       out  = (float*)d_out;

    __half *p_xh, *p_mean, *p_x1;
    __half *p_wl0, *p_wr0, *p_wl1, *p_wr1, *p_wc, *p_wo;
    int* p_cnt;
    cudaGetSymbolAddress((void**)&p_xh,   g_xh);
    cudaGetSymbolAddress((void**)&p_mean, g_meanh);
    cudaGetSymbolAddress((void**)&p_x1,   g_x1h);
    cudaGetSymbolAddress((void**)&p_wl0,  g_wl0h);
    cudaGetSymbolAddress((void**)&p_wr0,  g_wr0h);
    cudaGetSymbolAddress((void**)&p_wl1,  g_wl1h);
    cudaGetSymbolAddress((void**)&p_wr1,  g_wr1h);
    cudaGetSymbolAddress((void**)&p_wc,   g_wch);
    cudaGetSymbolAddress((void**)&p_wo,   g_woh);
    cudaGetSymbolAddress((void**)&p_cnt,  g_cnt);

    cudaFuncSetAttribute(k_layer,
                         cudaFuncAttributeMaxDynamicSharedMemorySize, SM_TOT);

    const int SCAN_NB = (NN + 1023) / 1024;
    const int GB = (NN + 127) / 128;

    // prep (x->fp16, weights->fp16, degree count + bucket ranks) + CSR build
    cudaMemsetAsync(p_cnt, 0, (NN + 1) * sizeof(int));
    k_prep<<<(NN * 32 + 255) / 256, 256>>>(x, ei, W_l0, W_r0, W_l1, W_r1, W_c, W_o);
    k_scan_block<<<SCAN_NB, 1024>>>();
    k_scan_add<<<SCAN_NB, 1024>>>();
    k_fill<<<(NE + 255) / 256, 256>>>(ei);     // atomic-free scatter

    // layer 0
    k_aggregate<<<(NN + 7) / 8, 256>>>(p_xh, p_mean);
    k_layer<<<GB, 256, SM_TOT>>>(p_xh, p_mean, p_wl0, p_wr0, p_wc, p_wo,
                                 b_l0, b_c, b_o, p_x1, NN, 0);
    // layer 1 (+ fused P/Q head)
    k_aggregate<<<(NN + 7) / 8, 256>>>(p_x1, p_mean);
    k_layer<<<GB, 256, SM_TOT>>>(p_x1, p_mean, p_wl1, p_wr1, p_wc, p_wo,
                                 b_l1, b_c, b_o, p_x1, NN, 1);

    // edge head: out = (P + b_o)[src] + Q[dst]
    k_edge<<<(2 * NE + 255) / 256, 256>>>(ei, out);
}

// round 17
// speedup vs baseline: 1.3714x; 1.3714x over previous
#include <cuda_runtime.h>
#include <cuda_fp16.h>
#include <cstdint>

#define NN 100000
#define NE 1000000
#define D  128

// ---------------- scratch (device globals; no allocations allowed) ----------
__device__ int    g_cnt[NN + 1];
__device__ int    g_off[NN + 2];
__device__ int    g_pos[NN];
__device__ int    g_srcs[NE];
__device__ int    g_part[128];
__device__ __half g_xh   [(size_t)NN * D];   // fp16 copy of input x
__device__ __half g_meanh[(size_t)NN * D];
__device__ __half g_x1h  [(size_t)NN * D];
__device__ __half g_P    [(size_t)NN * 16];  // fp16, P + b_o folded
__device__ __half g_Q    [(size_t)NN * 16];  // fp16
// fp16 weights (pre-converted once per call)
__device__ __half g_wl0h[128 * 128];
__device__ __half g_wr0h[128 * 128];
__device__ __half g_wl1h[128 * 128];
__device__ __half g_wr1h[128 * 128];
__device__ __half g_wch [128 * 256];
__device__ __half g_woh [32 * 128];          // r<16 = Wo[r][0:128], r>=16 = Wo[r-16][128:256]

// ---------------- helpers ----------------------------------------------------
__device__ __forceinline__ uint32_t smem_u32(const void* p) {
    uint32_t a;
    asm("{ .reg .u64 t; cvta.to.shared.u64 t, %1; cvt.u32.u64 %0, t; }"
        : "=r"(a) : "l"(p));
    return a;
}
__device__ __forceinline__ uint32_t pkh(float lo, float hi) {
    uint32_t d;  // bits[15:0]=f16(lo), bits[31:16]=f16(hi)
    asm("cvt.rn.f16x2.f32 %0, %1, %2;" : "=r"(d) : "f"(hi), "f"(lo));
    return d;
}
__device__ __forceinline__ void ldsm4(uint32_t* r, uint32_t addr) {
    asm volatile("ldmatrix.sync.aligned.m8n8.x4.shared.b16 {%0,%1,%2,%3}, [%4];"
                 : "=r"(r[0]), "=r"(r[1]), "=r"(r[2]), "=r"(r[3]) : "r"(addr));
}
__device__ __forceinline__ void mma_f16(float* d, const uint32_t* a,
                                        const uint32_t* b) {
    asm volatile(
        "mma.sync.aligned.m16n8k16.row.col.f32.f16.f16.f32 "
        "{%0,%1,%2,%3}, {%4,%5,%6,%7}, {%8,%9}, {%0,%1,%2,%3};"
        : "+f"(d[0]), "+f"(d[1]), "+f"(d[2]), "+f"(d[3])
        : "r"(a[0]), "r"(a[1]), "r"(a[2]), "r"(a[3]), "r"(b[0]), "r"(b[1]));
}

// ---------------- prep: x->fp16, all weights->fp16, zero counters ------------
__global__ void k_prep(const float* __restrict__ x,
                       const float* __restrict__ wl0, const float* __restrict__ wr0,
                       const float* __restrict__ wl1, const float* __restrict__ wr1,
                       const float* __restrict__ wc,  const float* __restrict__ wo) {
    int i = blockIdx.x * blockDim.x + threadIdx.x;
    if (i < NN * 32) {           // x: one float4 -> 4 halves
        float4 v = reinterpret_cast<const float4*>(x)[i];
        uint2 h;
        h.x = pkh(v.x, v.y);
        h.y = pkh(v.z, v.w);
        reinterpret_cast<uint2*>(g_xh)[i] = h;
    }
    if (i < 16384)       g_wl0h[i]         = __float2half(wl0[i]);
    else if (i < 32768)  g_wr0h[i - 16384] = __float2half(wr0[i - 16384]);
    else if (i < 49152)  g_wl1h[i - 32768] = __float2half(wl1[i - 32768]);
    else if (i < 65536)  g_wr1h[i - 49152] = __float2half(wr1[i - 49152]);
    else if (i < 98304)  g_wch[i - 65536]  = __float2half(wc[i - 65536]);
    else if (i < 102400) {       // Wo rearranged to [32,128]
        int j = i - 98304;
        int r = j >> 7, c = j & 127;
        float v = (r < 16) ? wo[(size_t)r * 256 + c]
                           : wo[(size_t)(r - 16) * 256 + 128 + c];
        g_woh[j] = __float2half(v);
    }
    if (i <= NN) g_cnt[i] = 0;
}

// ---------------- CSR build (edge_index is int32: JAX x64 disabled) ----------
__global__ void k_count(const int* __restrict__ ei) {
    int e = blockIdx.x * blockDim.x + threadIdx.x;
    if (e < NE) {
        unsigned d = (unsigned)ei[NE + e];
        if (d < NN) atomicAdd(&g_cnt[d], 1);
    }
}

__global__ void k_scan_block() {   // per-block exclusive scan of g_cnt -> g_off
    __shared__ int sh[1024];
    int i = blockIdx.x * 1024 + threadIdx.x;
    int v = (i < NN) ? g_cnt[i] : 0;
    sh[threadIdx.x] = v;
    __syncthreads();
    for (int off = 1; off < 1024; off <<= 1) {
        int t = (threadIdx.x >= off) ? sh[threadIdx.x - off] : 0;
        __syncthreads();
        sh[threadIdx.x] += t;
        __syncthreads();
    }
    if (i < NN) g_off[i] = sh[threadIdx.x] - v;   // exclusive
    if (threadIdx.x == 1023) g_part[blockIdx.x] = sh[1023];
}

__global__ void k_scan_add() {   // parallel scan over block partials
    __shared__ int sp[128];
    int b = blockIdx.x;
    int nb = gridDim.x;
    if (threadIdx.x < 128)
        sp[threadIdx.x] = (threadIdx.x < nb) ? g_part[threadIdx.x] : 0;
    __syncthreads();
    for (int off = 1; off < 128; off <<= 1) {
        int t = 0;
        if (threadIdx.x < 128 && threadIdx.x >= off) t = sp[threadIdx.x - off];
        __syncthreads();
        if (threadIdx.x < 128) sp[threadIdx.x] += t;
        __syncthreads();
    }
    int s_base = (b == 0) ? 0 : sp[b - 1];
    int i = b * 1024 + threadIdx.x;
    if (i < NN) {
        int o = g_off[i] + s_base;
        g_off[i] = o;
        g_pos[i] = o;
    }
    if (i == 0) g_off[NN] = NE;
}

__global__ void k_fill(const int* __restrict__ ei) {
    int e = blockIdx.x * blockDim.x + threadIdx.x;
    if (e < NE) {
        unsigned d = (unsigned)ei[NE + e];
        if (d < NN) {
            int p = atomicAdd(&g_pos[d], 1);
            if (p >= 0 && p < NE) g_srcs[p] = ei[e];
        }
    }
}

// ---------------- mean aggregation (fp16 rows): one warp per node ------------
__global__ void k_aggregate(const __half* __restrict__ xin,
                            __half* __restrict__ mout) {
    int n = blockIdx.x * (blockDim.x >> 5) + (threadIdx.x >> 5);
    if (n >= NN) return;
    int lane = threadIdx.x & 31;
    int beg = g_off[n], end = g_off[n + 1];
    float ax = 0.f, ay = 0.f, az = 0.f, aw = 0.f;
    #pragma unroll 4
    for (int t = beg; t < end; t++) {
        unsigned s = (unsigned)g_srcs[t];
        if (s >= NN) continue;
        uint2 v = *reinterpret_cast<const uint2*>(xin + (size_t)s * D + lane * 4);
        __half2 h0 = *reinterpret_cast<__half2*>(&v.x);
        __half2 h1 = *reinterpret_cast<__half2*>(&v.y);
        float2 f0 = __half22float2(h0), f1 = __half22float2(h1);
        ax += f0.x; ay += f0.y; az += f1.x; aw += f1.y;
    }
    int c = end - beg;
    float inv = 1.0f / (float)(c > 0 ? c : 1);
    uint2 o;
    o.x = pkh(ax * inv, ay * inv);
    o.y = pkh(az * inv, aw * inv);
    *reinterpret_cast<uint2*>(mout + (size_t)n * D + lane * 4) = o;
}

// ---------------- fused SAGE layer (+ optional fused P/Q head) ---------------
// h = relu([mean|x]W^T + bl) (SMEM only); x' = relu([x|h]Wc^T + bc).
// do_pq=0: write x' to OUT. do_pq=1: x' -> SMEM, then P/Q = x' x Wo^T (+b_o).
#define SROW   272
#define SX_OFF 0
#define SMH_OFF 34816
#define SB_OFF 69632
#define SM_TOT 104448

struct MmaCtx {
    uint32_t smb, aoff, boff;
    int m0, n0;
};

__device__ __forceinline__ void mma_tiles(const MmaCtx& c, uint32_t a_off_base,
                                          float acc[2][8][4]) {
    #pragma unroll
    for (int ks = 0; ks < 8; ks++) {
        uint32_t a0[4], a1[4], bf[4][4];
        ldsm4(a0, c.smb + a_off_base + (uint32_t)(c.m0 * SROW) + ks * 32 + c.aoff);
        ldsm4(a1, c.smb + a_off_base + (uint32_t)((c.m0 + 16) * SROW) + ks * 32 + c.aoff);
        #pragma unroll
        for (int nb = 0; nb < 4; nb++)
            ldsm4(bf[nb], c.smb + SB_OFF + (uint32_t)((c.n0 + nb * 16) * SROW)
                          + ks * 32 + c.boff);
        #pragma unroll
        for (int nb = 0; nb < 4; nb++) {
            mma_f16(acc[0][nb * 2 + 0], a0, &bf[nb][0]);
            mma_f16(acc[0][nb * 2 + 1], a0, &bf[nb][2]);
            mma_f16(acc[1][nb * 2 + 0], a1, &bf[nb][0]);
            mma_f16(acc[1][nb * 2 + 1], a1, &bf[nb][2]);
        }
    }
}

__device__ __forceinline__ void load_b(char* sm, const __half* __restrict__ w,
                                       int stride, int tid) {
    #pragma unroll
    for (int i = 0; i < 8; i++) {
        int idx = tid + i * 256;          // 0..2047
        int r = idx >> 4, cc = idx & 15;
        uint4 v = *reinterpret_cast<const uint4*>(w + (size_t)r * stride + cc * 8);
        *reinterpret_cast<uint4*>(sm + SB_OFF + r * SROW + cc * 16) = v;
    }
}

__global__ void __launch_bounds__(256, 2) k_layer(
    const __half* __restrict__ X, const __half* __restrict__ MEAN,
    const __half* __restrict__ Wl, const __half* __restrict__ Wr,
    const __half* __restrict__ Wc, const __half* __restrict__ Wo,
    const float* __restrict__ bl, const float* __restrict__ bc,
    const float* __restrict__ bo,
    __half* __restrict__ OUT, int nrows, int do_pq)
{
    extern __shared__ __align__(16) char sm[];
    uint32_t smb = smem_u32(sm);
    int tid = threadIdx.x, lane = tid & 31, wid = tid >> 5;
    int row0 = blockIdx.x * 128;

    MmaCtx c;
    c.smb = smb;
    c.m0 = (wid >> 1) * 32;
    c.n0 = (wid & 1) * 64;
    {
        int t = lane >> 3, rr = lane & 7;
        c.aoff = (uint32_t)((lane & 15) * SROW + (lane >> 4) * 16);
        c.boff = (uint32_t)((((t >> 1) * 8 + rr) * SROW) + (t & 1) * 16);
    }

    // load x and mean tiles (fp16 straight copies)
    #pragma unroll
    for (int i = 0; i < 8; i++) {
        int idx = tid + i * 256;
        int r = idx >> 4, cc = idx & 15;
        int gr = row0 + r;
        uint4 vx = make_uint4(0u, 0u, 0u, 0u), vm = vx;
        if (gr < nrows) {
            vx = *reinterpret_cast<const uint4*>(X + (size_t)gr * D + cc * 8);
            vm = *reinterpret_cast<const uint4*>(MEAN + (size_t)gr * D + cc * 8);
        }
        *reinterpret_cast<uint4*>(sm + SX_OFF + r * SROW + cc * 16) = vx;
        *reinterpret_cast<uint4*>(sm + SMH_OFF + r * SROW + cc * 16) = vm;
    }
    load_b(sm, Wl, 128, tid);
    __syncthreads();

    float acc[2][8][4];
    #pragma unroll
    for (int i = 0; i < 2; i++)
        #pragma unroll
        for (int j = 0; j < 8; j++)
            #pragma unroll
            for (int q = 0; q < 4; q++) acc[i][j][q] = 0.f;

    // GEMM1 phase a: mean x Wl
    mma_tiles(c, SMH_OFF, acc);
    __syncthreads();
    load_b(sm, Wr, 128, tid);
    __syncthreads();
    // GEMM1 phase b: x x Wr
    mma_tiles(c, SX_OFF, acc);

    // epilogue 1: h = relu(acc + bl) -> SMEM (overwrites mean tile)
    #pragma unroll
    for (int mi = 0; mi < 2; mi++) {
        int r0 = c.m0 + mi * 16 + (lane >> 2);
        #pragma unroll
        for (int f = 0; f < 8; f++) {
            int col = c.n0 + f * 8 + (lane & 3) * 2;
            float2 bv = *reinterpret_cast<const float2*>(bl + col);
            uint32_t h0 = pkh(fmaxf(acc[mi][f][0] + bv.x, 0.f),
                              fmaxf(acc[mi][f][1] + bv.y, 0.f));
            uint32_t h1 = pkh(fmaxf(acc[mi][f][2] + bv.x, 0.f),
                              fmaxf(acc[mi][f][3] + bv.y, 0.f));
            *reinterpret_cast<uint32_t*>(sm + SMH_OFF + r0 * SROW + col * 2) = h0;
            *reinterpret_cast<uint32_t*>(sm + SMH_OFF + (r0 + 8) * SROW + col * 2) = h1;
        }
    }
    __syncthreads();
    load_b(sm, Wc, 256, tid);          // Wc k-cols [0,128) -> multiplies x
    __syncthreads();

    #pragma unroll
    for (int i = 0; i < 2; i++)
        #pragma unroll
        for (int j = 0; j < 8; j++)
            #pragma unroll
            for (int q = 0; q < 4; q++) acc[i][j][q] = 0.f;

    // GEMM2 phase a: x x Wc1
    mma_tiles(c, SX_OFF, acc);
    __syncthreads();
    load_b(sm, Wc + 128, 256, tid);    // Wc k-cols [128,256) -> multiplies h
    __syncthreads();
    // GEMM2 phase b: h x Wc2
    mma_tiles(c, SMH_OFF, acc);

    if (!do_pq) {
        // epilogue 2: x' = relu(acc + bc) -> global fp16
        #pragma unroll
        for (int mi = 0; mi < 2; mi++) {
            int gr0 = row0 + c.m0 + mi * 16 + (lane >> 2);
            #pragma unroll
            for (int f = 0; f < 8; f++) {
                int col = c.n0 + f * 8 + (lane & 3) * 2;
                float2 bv = *reinterpret_cast<const float2*>(bc + col);
                if (gr0 < nrows) {
                    uint32_t h = pkh(fmaxf(acc[mi][f][0] + bv.x, 0.f),
                                     fmaxf(acc[mi][f][1] + bv.y, 0.f));
                    *reinterpret_cast<uint32_t*>(OUT + (size_t)gr0 * D + col) = h;
                }
                if (gr0 + 8 < nrows) {
                    uint32_t h = pkh(fmaxf(acc[mi][f][2] + bv.x, 0.f),
                                     fmaxf(acc[mi][f][3] + bv.y, 0.f));
                    *reinterpret_cast<uint32_t*>(OUT + (size_t)(gr0 + 8) * D + col) = h;
                }
            }
        }
        return;
    }

    // ---- fused P/Q head: x' -> SMEM (SX region), then [128x128] x Wo^T -----
    __syncthreads();
    #pragma unroll
    for (int mi = 0; mi < 2; mi++) {
        int r0 = c.m0 + mi * 16 + (lane >> 2);
        #pragma unroll
        for (int f = 0; f < 8; f++) {
            int col = c.n0 + f * 8 + (lane & 3) * 2;
            float2 bv = *reinterpret_cast<const float2*>(bc + col);
            uint32_t h0 = pkh(fmaxf(acc[mi][f][0] + bv.x, 0.f),
                              fmaxf(acc[mi][f][1] + bv.y, 0.f));
            uint32_t h1 = pkh(fmaxf(acc[mi][f][2] + bv.x, 0.f),
                              fmaxf(acc[mi][f][3] + bv.y, 0.f));
            *reinterpret_cast<uint32_t*>(sm + SX_OFF + r0 * SROW + col * 2) = h0;
            *reinterpret_cast<uint32_t*>(sm + SX_OFF + (r0 + 8) * SROW + col * 2) = h1;
        }
    }
    // Wo tile: 32 rows x 128 halves
    #pragma unroll
    for (int i = 0; i < 2; i++) {
        int idx = tid + i * 256;          // 0..511
        int r = idx >> 4, cc = idx & 15;
        uint4 v = *reinterpret_cast<const uint4*>(Wo + (size_t)r * 128 + cc * 8);
        *reinterpret_cast<uint4*>(sm + SB_OFF + r * SROW + cc * 16) = v;
    }
    __syncthreads();

    int m0 = wid * 16;
    float pq[4][4];
    #pragma unroll
    for (int j = 0; j < 4; j++)
        #pragma unroll
        for (int q = 0; q < 4; q++) pq[j][q] = 0.f;

    #pragma unroll
    for (int ks = 0; ks < 8; ks++) {
        uint32_t a0[4], bf[2][4];
        ldsm4(a0, smb + SX_OFF + (uint32_t)(m0 * SROW) + ks * 32 + c.aoff);
        ldsm4(bf[0], smb + SB_OFF + ks * 32 + c.boff);
        ldsm4(bf[1], smb + SB_OFF + (uint32_t)(16 * SROW) + ks * 32 + c.boff);
        mma_f16(pq[0], a0, &bf[0][0]);
        mma_f16(pq[1], a0, &bf[0][2]);
        mma_f16(pq[2], a0, &bf[1][0]);
        mma_f16(pq[3], a0, &bf[1][2]);
    }

    // epilogue: cols 0..15 -> P (+= b_o, fp16), cols 16..31 -> Q (fp16)
    int gr0 = row0 + m0 + (lane >> 2);
    #pragma unroll
    for (int f = 0; f < 4; f++) {
        int col = f * 8 + (lane & 3) * 2;   // 0..30
        #pragma unroll
        for (int half = 0; half < 2; half++) {
            int gr = gr0 + half * 8;
            if (gr >= nrows) continue;
            float vx = pq[f][half * 2 + 0];
            float vy = pq[f][half * 2 + 1];
            if (col < 16) {
                float2 bv = *reinterpret_cast<const float2*>(bo + col);
                uint32_t h = pkh(vx + bv.x, vy + bv.y);
                *reinterpret_cast<uint32_t*>(g_P + (size_t)gr * 16 + col) = h;
            } else {
                uint32_t h = pkh(vx, vy);
                *reinterpret_cast<uint32_t*>(g_Q + (size_t)gr * 16 + (col - 16)) = h;
            }
        }
    }
}

// ---------------- edge head: out[e] = P'[src] + Q[dst] (fp16 rows) -----------
// One thread per edge: single index-pair load, 2x16B from P, 2x16B from Q.
__global__ void k_edge(const int* __restrict__ ei, float* __restrict__ out) {
    int e = blockIdx.x * blockDim.x + threadIdx.x;
    if (e >= NE) return;
    unsigned s = (unsigned)ei[e];
    unsigned d = (unsigned)ei[NE + e];
    uint4 ph[2], qh[2];
    ph[0] = ph[1] = qh[0] = qh[1] = make_uint4(0u, 0u, 0u, 0u);
    if (s < NN) {
        ph[0] = reinterpret_cast<const uint4*>(g_P)[(size_t)s * 2 + 0];
        ph[1] = reinterpret_cast<const uint4*>(g_P)[(size_t)s * 2 + 1];
    }
    if (d < NN) {
        qh[0] = reinterpret_cast<const uint4*>(g_Q)[(size_t)d * 2 + 0];
        qh[1] = reinterpret_cast<const uint4*>(g_Q)[(size_t)d * 2 + 1];
    }
    float4* dst = reinterpret_cast<float4*>(out) + (size_t)e * 4;
    #pragma unroll
    for (int h = 0; h < 2; h++) {
        const uint32_t* pw = &ph[h].x;
        const uint32_t* qw = &qh[h].x;
        #pragma unroll
        for (int j = 0; j < 2; j++) {
            float2 pa = __half22float2(*reinterpret_cast<const __half2*>(&pw[j * 2 + 0]));
            float2 pb = __half22float2(*reinterpret_cast<const __half2*>(&pw[j * 2 + 1]));
            float2 qa = __half22float2(*reinterpret_cast<const __half2*>(&qw[j * 2 + 0]));
            float2 qb = __half22float2(*reinterpret_cast<const __half2*>(&qw[j * 2 + 1]));
            float4 o;
            o.x = pa.x + qa.x; o.y = pa.y + qa.y;
            o.z = pb.x + qb.x; o.w = pb.y + qb.y;
            __stcs(dst + h * 2 + j, o);
        }
    }
}

// ---------------- launch -----------------------------------------------------
extern "C" void kernel_launch(void* const* d_in, const int* in_sizes, int n_in,
                              void* d_out, int out_size) {
    const float* x    = (const float*)d_in[0];
    const int*   ei   = (const int*)d_in[1];     // int32: JAX x64 is disabled
    const float* W_l0 = (const float*)d_in[2];
    const float* b_l0 = (const float*)d_in[3];
    const float* W_r0 = (const float*)d_in[4];
    const float* W_l1 = (const float*)d_in[5];
    const float* b_l1 = (const float*)d_in[6];
    const float* W_r1 = (const float*)d_in[7];
    const float* W_c  = (const float*)d_in[8];
    const float* b_c  = (const float*)d_in[9];
    const float* W_o  = (const float*)d_in[10];
    const float* b_o  = (const float*)d_in[11];
    float*       out  = (float*)d_out;

    __half *p_xh, *p_mean, *p_x1;
    __half *p_wl0, *p_wr0, *p_wl1, *p_wr1, *p_wc, *p_wo;
    cudaGetSymbolAddress((void**)&p_xh,   g_xh);
    cudaGetSymbolAddress((void**)&p_mean, g_meanh);
    cudaGetSymbolAddress((void**)&p_x1,   g_x1h);
    cudaGetSymbolAddress((void**)&p_wl0,  g_wl0h);
    cudaGetSymbolAddress((void**)&p_wr0,  g_wr0h);
    cudaGetSymbolAddress((void**)&p_wl1,  g_wl1h);
    cudaGetSymbolAddress((void**)&p_wr1,  g_wr1h);
    cudaGetSymbolAddress((void**)&p_wc,   g_wch);
    cudaGetSymbolAddress((void**)&p_wo,   g_woh);

    cudaFuncSetAttribute(k_layer,
                         cudaFuncAttributeMaxDynamicSharedMemorySize, SM_TOT);

    const int SCAN_NB = (NN + 1023) / 1024;
    const int GB = (NN + 127) / 128;

    // launch 1: prep (x->fp16, weights->fp16, counters zeroed)
    k_prep<<<(NN * 32 + 255) / 256, 256>>>(x, W_l0, W_r0, W_l1, W_r1, W_c, W_o);
    // launches 2-5: CSR build
    k_count<<<(NE + 255) / 256, 256>>>(ei);
    k_scan_block<<<SCAN_NB, 1024>>>();
    k_scan_add<<<SCAN_NB, 1024>>>();
    k_fill<<<(NE + 255) / 256, 256>>>(ei);

    // launch 6: aggregate
    k_aggregate<<<(NN + 7) / 8, 256>>>(p_xh, p_mean);
    // layer 0
    k_layer<<<GB, 256, SM_TOT>>>(p_xh, p_mean, p_wl0, p_wr0, p_wc, p_wo,
                                 b_l0, b_c, b_o, p_x1, NN, 0);
    // layer 1 (+ fused P/Q head)
    k_aggregate<<<(NN + 7) / 8, 256>>>(p_x1, p_mean);
    k_layer<<<GB, 256, SM_TOT>>>(p_x1, p_mean, p_wl1, p_wr1, p_wc, p_wo,
                                 b_l1, b_c, b_o, p_x1, NN, 1);

    // edge head: out = (P + b_o)[src] + Q[dst]
    k_edge<<<(NE + 255) / 256, 256>>>(ei, out);
}